// round 14
// baseline (speedup 1.0000x reference)
#include <cuda_runtime.h>
#include <cuda_bf16.h>
#include <cstdint>

// Problem constants
#define Bn   256
#define Cn   512
#define Nn   49          // 7x7 attention positions
#define HWn  196         // 14*14
#define Mrows (Bn*Nn)    // 12544

// Scratch (no allocation allowed)
__device__ float          g_a [Mrows * Cn];    // pooled fp32 (final einsum)
__device__ __nv_bfloat16  g_ab[Mrows * Cn];    // pooled bf16 (GEMM A)
__device__ __nv_bfloat16  g_wb[Cn * Cn];       // Wa bf16 (GEMM B)
__device__ float          g_ah[Bn * Cn];       // h@Wh^T + bh + ba
__device__ float          g_spart[16 * Mrows]; // per (col-tile, col-half) partials

__device__ __forceinline__ float fast_tanh(float x) {
    float y; asm("tanh.approx.f32 %0, %1;" : "=f"(y) : "f"(x)); return y;
}
__device__ __forceinline__ uint32_t smem_u32(const void* p) {
    uint32_t a;
    asm("{ .reg .u64 t; cvta.to.shared.u64 t, %1; cvt.u32.u64 %0, t; }" : "=r"(a) : "l"(p));
    return a;
}
__device__ __forceinline__ void cp16(uint32_t dst, const void* src) {
    asm volatile("cp.async.cg.shared.global [%0], [%1], 16;" :: "r"(dst), "l"(src));
}
__device__ __forceinline__ void ldsm4(uint32_t& r0, uint32_t& r1, uint32_t& r2,
                                      uint32_t& r3, uint32_t addr) {
    asm volatile("ldmatrix.sync.aligned.m8n8.x4.shared.b16 {%0,%1,%2,%3}, [%4];"
                 : "=r"(r0), "=r"(r1), "=r"(r2), "=r"(r3) : "r"(addr));
}
__device__ __forceinline__ void mma_bf16(float* d, const uint32_t* a, const uint32_t* b) {
    asm volatile(
        "mma.sync.aligned.m16n8k16.row.col.f32.bf16.bf16.f32 "
        "{%0,%1,%2,%3}, {%4,%5,%6,%7}, {%8,%9}, {%0,%1,%2,%3};"
        : "+f"(d[0]), "+f"(d[1]), "+f"(d[2]), "+f"(d[3])
        : "r"(a[0]), "r"(a[1]), "r"(a[2]), "r"(a[3]), "r"(b[0]), "r"(b[1]));
}

// ---------------------------------------------------------------------------
// K0 "misc": Wa->bf16 convert (blocks 0..255) + h2a (blocks 256..767)
// ---------------------------------------------------------------------------
__global__ __launch_bounds__(256) void misc_kernel(const float* __restrict__ Wa,
                                                   const float* __restrict__ h,
                                                   const float* __restrict__ Wh,
                                                   const float* __restrict__ bh,
                                                   const float* __restrict__ ba) {
    __shared__ struct { float sh[16][132]; float sw[16][132]; } u;
    int blk = blockIdx.x;
    int tid = threadIdx.x;

    if (blk < 256) {
        int i = blk * 1024 + tid * 4;
        float4 v = *(const float4*)(Wa + i);
        __nv_bfloat162 lo(__float2bfloat16_rn(v.x), __float2bfloat16_rn(v.y));
        __nv_bfloat162 hi(__float2bfloat16_rn(v.z), __float2bfloat16_rn(v.w));
        uint2 pk;
        pk.x = *(uint32_t*)&lo;
        pk.y = *(uint32_t*)&hi;
        *(uint2*)(g_wb + i) = pk;
    } else {
        int blk2 = blk - 256;                       // 0..511
        int d0 = (blk2 >> 4) * 16, b0 = (blk2 & 15) * 16;
        int tx = tid & 15, ty = tid >> 4;
        float acc = 0.f;
        for (int c0 = 0; c0 < Cn; c0 += 128) {
#pragma unroll
            for (int p = 0; p < 2; ++p) {
                int i = tid + p * 256;
                int r = i >> 5;
                int cc = (i & 31) * 4;
                *(float4*)&u.sh[r][cc] = *(const float4*)&h [(size_t)(b0 + r) * Cn + c0 + cc];
                *(float4*)&u.sw[r][cc] = *(const float4*)&Wh[(size_t)(d0 + r) * Cn + c0 + cc];
            }
            __syncthreads();
#pragma unroll
            for (int c = 0; c < 128; ++c) acc += u.sh[ty][c] * u.sw[tx][c];
            __syncthreads();
        }
        int d = d0 + tx, b = b0 + ty;
        g_ah[(size_t)b * Cn + d] = acc + bh[d] + ba[d];
    }
}

// ---------------------------------------------------------------------------
// K1 "pool chunk": 2x2 avg pool of 64 batches starting at bBase.
// grid 1024 = (16 c-tiles) x (64 batches). Round-11 cp.async staging.
// ---------------------------------------------------------------------------
__global__ __launch_bounds__(256) void pool_kernel(const float* __restrict__ att_v,
                                                   int bBase) {
    __shared__ struct { float4 raw[32 * 49]; float pooled[32][51]; } u;
    int tid = threadIdx.x;
    int c0 = (blockIdx.x & 15) * 32;
    int b  = bBase + (blockIdx.x >> 4);
    const float4* base = (const float4*)(att_v + ((size_t)b * Cn + c0) * HWn);
    uint32_t raw_s = smem_u32(u.raw);

    // dense cp.async staging: 1568 contiguous 16B chunks
#pragma unroll
    for (int t = 0; t < 7; ++t) {
        int idx = tid + t * 256;
        if (t < 6 || idx < 1568)
            cp16(raw_s + idx * 16, base + idx);
    }
    asm volatile("cp.async.commit_group;" ::: "memory");
    asm volatile("cp.async.wait_group 0;" ::: "memory");
    __syncthreads();

    // pool from smem: thread = (channel, pooled-row); 7 LDS.128
    int cl = tid >> 3;
    int ii = tid & 7;
    if (ii < 7) {
        const float4* p = &u.raw[cl * 49 + ii * 7];
        float4 v0 = p[0], v1 = p[1], v2 = p[2], v3 = p[3],
               v4 = p[4], v5 = p[5], v6 = p[6];
        float r0 = (v0.x + v0.y + v3.z + v3.w) * 0.25f;
        float r1 = (v0.z + v0.w + v4.x + v4.y) * 0.25f;
        float r2 = (v1.x + v1.y + v4.z + v4.w) * 0.25f;
        float r3 = (v1.z + v1.w + v5.x + v5.y) * 0.25f;
        float r4 = (v2.x + v2.y + v5.z + v5.w) * 0.25f;
        float r5 = (v2.z + v2.w + v6.x + v6.y) * 0.25f;
        float r6 = (v3.x + v3.y + v6.z + v6.w) * 0.25f;
        float* row = &u.pooled[cl][ii * 7];
        row[0] = r0; row[1] = r1; row[2] = r2; row[3] = r3;
        row[4] = r4; row[5] = r5; row[6] = r6;
    }
    __syncthreads();
    // write phase: 392 float4 (n-major, 8 channel-quads); conflict-free LDS
    for (int idx = tid; idx < Nn * 8; idx += 256) {
        int n = idx >> 3, c4 = idx & 7;
        float4 v;
        v.x = u.pooled[c4 * 4 + 0][n];
        v.y = u.pooled[c4 * 4 + 1][n];
        v.z = u.pooled[c4 * 4 + 2][n];
        v.w = u.pooled[c4 * 4 + 3][n];
        size_t o = (size_t)(b * Nn + n) * Cn + c0 + c4 * 4;
        *(float4*)(g_a + o) = v;
        __nv_bfloat162 lo(__float2bfloat16_rn(v.x), __float2bfloat16_rn(v.y));
        __nv_bfloat162 hi(__float2bfloat16_rn(v.z), __float2bfloat16_rn(v.w));
        uint2 pk;
        pk.x = *(uint32_t*)&lo;
        pk.y = *(uint32_t*)&hi;
        *(uint2*)(g_ab + o) = pk;
    }
}

// ---------------------------------------------------------------------------
// K3: bf16 mma.sync GEMM + tanh + dot(Wd). BM=128, BN=64, BK=64.
// 3-stage cp.async ring, XOR-swizzled 128B-pitch smem, 1 barrier/stage.
// 8 warps = 4(M) x 2(N:32 each). grid (8, nTiles); row-tile = tileBase+by.
// ---------------------------------------------------------------------------
#define STG_A    16384       // 128 rows * 128B
#define STG_B    8192        // 64 rows * 128B
#define STG_BOTH 24576
#define OFF_AH   73728       // 3 stages * 24576
#define OFF_WD   74752       // + 4*64*4
#define SMEM_SZ  75264

__global__ __launch_bounds__(256, 2) void gemm_score_kernel(const float* __restrict__ Wd,
                                                            int tileBase) {
    extern __shared__ __align__(16) char smem[];
    uint32_t sb = smem_u32(smem);
    float* sAh = (float*)(smem + OFF_AH);
    float* sWd = (float*)(smem + OFF_WD);

    int tid  = threadIdx.x;
    int lane = tid & 31;
    int warp = tid >> 5;
    int warpM = warp & 3;
    int warpC = warp >> 2;
    int rowBase = (tileBase + blockIdx.y) * 128;
    int colBase = blockIdx.x * 64;
    int b0 = rowBase / Nn;

    for (int i = tid; i < 4 * 64; i += 256) {
        int bb = i >> 6, c = i & 63;
        int b = b0 + bb;
        sAh[i] = (b < Bn) ? g_ah[(size_t)b * Cn + colBase + c] : 0.f;
    }
    if (tid < 64) sWd[tid] = Wd[colBase + tid];

    const __nv_bfloat16* gA = g_ab + (size_t)rowBase * Cn;
    const __nv_bfloat16* gB = g_wb + (size_t)colBase * Cn;

    auto load_stage = [&](int s, int buf) {
        uint32_t base = sb + buf * STG_BOTH;
#pragma unroll
        for (int t = 0; t < 4; ++t) {
            int c2 = tid + t * 256;                 // 0..1023 (A)
            int r  = c2 >> 3;
            int cc = c2 & 7;
            uint32_t dsw = (uint32_t)(r * 128 + ((cc ^ (r & 7)) << 4));
            cp16(base + dsw, gA + (size_t)r * Cn + s * 64 + cc * 8);
        }
#pragma unroll
        for (int t = 0; t < 2; ++t) {
            int c2 = tid + t * 256;                 // 0..511 (B)
            int r  = c2 >> 3;
            int cc = c2 & 7;
            uint32_t dsw = (uint32_t)(r * 128 + ((cc ^ (r & 7)) << 4));
            cp16(base + STG_A + dsw, gB + (size_t)r * Cn + s * 64 + cc * 8);
        }
        asm volatile("cp.async.commit_group;" ::: "memory");
    };

    float acc[2][4][4];
#pragma unroll
    for (int mi = 0; mi < 2; ++mi)
#pragma unroll
        for (int ni = 0; ni < 4; ++ni)
#pragma unroll
            for (int q = 0; q < 4; ++q) acc[mi][ni][q] = 0.f;

    uint32_t s7 = lane & 7;
    uint32_t rowA = (uint32_t)(warpM * 32 + (lane & 15)) * 128;
    uint32_t rowB = STG_A +
                    (uint32_t)(warpC * 32 + ((lane >> 4) << 3) + (lane & 7)) * 128;
    uint32_t chA = lane >> 4;
    uint32_t chB = (lane >> 3) & 1;

    load_stage(0, 0);
    load_stage(1, 1);

#pragma unroll 1
    for (int s = 0; s < 8; ++s) {
        int buf = s - (s >= 3 ? 3 : 0) - (s >= 6 ? 3 : 0);   // s % 3
        if (s < 7) asm volatile("cp.async.wait_group 1;" ::: "memory");
        else       asm volatile("cp.async.wait_group 0;" ::: "memory");
        __syncthreads();

        uint32_t stage = sb + (uint32_t)buf * STG_BOTH;
#pragma unroll
        for (int kk = 0; kk < 4; ++kk) {
            uint32_t cA = (((2 * kk + chA) ^ s7) << 4);
            uint32_t cB = (((2 * kk + chB) ^ s7) << 4);
            uint32_t af[2][4], bf[4][2];
#pragma unroll
            for (int mi = 0; mi < 2; ++mi)
                ldsm4(af[mi][0], af[mi][1], af[mi][2], af[mi][3],
                      stage + rowA + mi * (16 * 128) + cA);
#pragma unroll
            for (int np = 0; np < 2; ++np)
                ldsm4(bf[2 * np][0], bf[2 * np][1], bf[2 * np + 1][0], bf[2 * np + 1][1],
                      stage + rowB + np * (16 * 128) + cB);
#pragma unroll
            for (int mi = 0; mi < 2; ++mi)
#pragma unroll
                for (int ni = 0; ni < 4; ++ni)
                    mma_bf16(acc[mi][ni], af[mi], bf[ni]);
        }
        if (s + 2 < 8) {
            int nbuf = buf + 2; if (nbuf >= 3) nbuf -= 3;
            load_stage(s + 2, nbuf);
        }
    }

    // Epilogue
    int gid = lane >> 2;
    int kq0 = (lane & 3) * 2;
    int slice = blockIdx.x * 2 + warpC;      // 0..15
#pragma unroll
    for (int mi = 0; mi < 2; ++mi) {
#pragma unroll
        for (int hh = 0; hh < 2; ++hh) {
            int rloc = warpM * 32 + mi * 16 + hh * 8 + gid;
            int grow = rowBase + rloc;
            int bb = grow / Nn - b0;
            float s = 0.f;
#pragma unroll
            for (int ni = 0; ni < 4; ++ni) {
                int cl = warpC * 32 + ni * 8 + kq0;
                s += fast_tanh(acc[mi][ni][hh * 2 + 0] + sAh[bb * 64 + cl])     * sWd[cl];
                s += fast_tanh(acc[mi][ni][hh * 2 + 1] + sAh[bb * 64 + cl + 1]) * sWd[cl + 1];
            }
            s += __shfl_xor_sync(0xffffffffu, s, 1);
            s += __shfl_xor_sync(0xffffffffu, s, 2);
            if ((lane & 3) == 0)
                g_spart[(size_t)slice * Mrows + grow] = s;
        }
    }
}

// ---------------------------------------------------------------------------
// K4: scores = sum(16 partials) + bd; warp softmax; float4 einsum
// ---------------------------------------------------------------------------
__global__ __launch_bounds__(128) void softmax_out_kernel(const float* __restrict__ bd,
                                                          float* __restrict__ out) {
    int b   = blockIdx.x;
    int tid = threadIdx.x;
    __shared__ float w[Nn];
    __shared__ float sinv_s;

    if (tid < Nn) {
        float s = bd[0];
#pragma unroll
        for (int i = 0; i < 16; ++i) s += g_spart[(size_t)i * Mrows + b * Nn + tid];
        w[tid] = s;
    }
    __syncthreads();
    if (tid < 32) {
        float x = w[tid];
        float y = (tid + 32 < Nn) ? w[tid + 32] : -1e30f;
        float m = fmaxf(x, y);
#pragma unroll
        for (int off = 16; off > 0; off >>= 1)
            m = fmaxf(m, __shfl_xor_sync(0xffffffffu, m, off));
        float e0 = __expf(x - m);
        float e1 = __expf(y - m);
        float s = e0 + e1;
#pragma unroll
        for (int off = 16; off > 0; off >>= 1)
            s += __shfl_xor_sync(0xffffffffu, s, off);
        w[tid] = e0;
        if (tid + 32 < Nn) w[tid + 32] = e1;
        if (tid == 0) sinv_s = 1.0f / s;
    }
    __syncthreads();
    float inv = sinv_s;

    int c = tid * 4;
    const float* ab = g_a + (size_t)b * Nn * Cn + c;
    float4 o = make_float4(0.f, 0.f, 0.f, 0.f);
#pragma unroll 7
    for (int n = 0; n < Nn; ++n) {
        float4 v = *(const float4*)(ab + (size_t)n * Cn);
        float wn = w[n];
        o.x += v.x * wn; o.y += v.y * wn; o.z += v.z * wn; o.w += v.w * wn;
    }
    o.x *= inv; o.y *= inv; o.z *= inv; o.w *= inv;
    *(float4*)(out + (size_t)b * Cn + c) = o;
}

// ---------------------------------------------------------------------------
// Launch: fork/join pipeline. Stream 0 (capture stream): misc, pool chunks.
// Stream s2: gemm chunk i after pool chunk i. Softmax joins both.
// Row-tile chunks (batches fully pooled per chunk): [0,24) [24,49) [49,73) [73,98)
// ---------------------------------------------------------------------------
extern "C" void kernel_launch(void* const* d_in, const int* in_sizes, int n_in,
                              void* d_out, int out_size) {
    const float* att_v = (const float*)d_in[0];
    const float* h     = (const float*)d_in[1];
    const float* Wa    = (const float*)d_in[2];
    const float* ba    = (const float*)d_in[3];
    const float* Wh    = (const float*)d_in[4];
    const float* bh    = (const float*)d_in[5];
    const float* Wd    = (const float*)d_in[6];
    const float* bd    = (const float*)d_in[7];
    float* out = (float*)d_out;

    static cudaStream_t s2 = nullptr;
    static cudaEvent_t  eP[4], eG;
    static bool init = false;
    if (!init) {
        cudaStreamCreateWithFlags(&s2, cudaStreamNonBlocking);
        for (int i = 0; i < 4; ++i)
            cudaEventCreateWithFlags(&eP[i], cudaEventDisableTiming);
        cudaEventCreateWithFlags(&eG, cudaEventDisableTiming);
        cudaFuncSetAttribute(gemm_score_kernel,
                             cudaFuncAttributeMaxDynamicSharedMemorySize, SMEM_SZ);
        init = true;
    }

    static const int tileStart[4] = {0, 24, 49, 73};
    static const int tileCnt [4] = {24, 25, 24, 25};

    // misc (wb + ah) on the capture stream: gemm chunks inherit this dep
    // via eP[0] (recorded after misc + pool0 on the same stream).
    misc_kernel<<<768, 256>>>(Wa, h, Wh, bh, ba);

    for (int i = 0; i < 4; ++i) {
        pool_kernel<<<1024, 256>>>(att_v, i * 64);
        cudaEventRecord(eP[i], 0);
        cudaStreamWaitEvent(s2, eP[i], 0);
        gemm_score_kernel<<<dim3(8, tileCnt[i]), 256, SMEM_SZ, s2>>>(Wd, tileStart[i]);
    }
    cudaEventRecord(eG, s2);
    cudaStreamWaitEvent(0, eG, 0);

    softmax_out_kernel<<<256, 128>>>(bd, out);
}

// round 15
// speedup vs baseline: 1.0246x; 1.0246x over previous
#include <cuda_runtime.h>
#include <cuda_bf16.h>
#include <cstdint>

// Problem constants
#define Bn   256
#define Cn   512
#define Nn   49          // 7x7 attention positions
#define HWn  196         // 14*14
#define Mrows (Bn*Nn)    // 12544

// Scratch (no allocation allowed)
__device__ float          g_a [Mrows * Cn];    // pooled fp32 (final einsum)
__device__ __nv_bfloat16  g_ab[Mrows * Cn];    // pooled bf16 (GEMM A)
__device__ __nv_bfloat16  g_wb[Cn * Cn];       // Wa bf16 (GEMM B)
__device__ float          g_ah[Bn * Cn];       // h@Wh^T + bh + ba
__device__ float          g_spart[32 * Mrows]; // per (col-tile, warp-col) partials

__device__ __forceinline__ float fast_tanh(float x) {
    float y; asm("tanh.approx.f32 %0, %1;" : "=f"(y) : "f"(x)); return y;
}
__device__ __forceinline__ uint32_t smem_u32(const void* p) {
    uint32_t a;
    asm("{ .reg .u64 t; cvta.to.shared.u64 t, %1; cvt.u32.u64 %0, t; }" : "=r"(a) : "l"(p));
    return a;
}
__device__ __forceinline__ void cp16(uint32_t dst, const void* src) {
    asm volatile("cp.async.cg.shared.global [%0], [%1], 16;" :: "r"(dst), "l"(src));
}
__device__ __forceinline__ void ldsm4(uint32_t& r0, uint32_t& r1, uint32_t& r2,
                                      uint32_t& r3, uint32_t addr) {
    asm volatile("ldmatrix.sync.aligned.m8n8.x4.shared.b16 {%0,%1,%2,%3}, [%4];"
                 : "=r"(r0), "=r"(r1), "=r"(r2), "=r"(r3) : "r"(addr));
}
__device__ __forceinline__ void mma_bf16(float* d, const uint32_t* a, const uint32_t* b) {
    asm volatile(
        "mma.sync.aligned.m16n8k16.row.col.f32.bf16.bf16.f32 "
        "{%0,%1,%2,%3}, {%4,%5,%6,%7}, {%8,%9}, {%0,%1,%2,%3};"
        : "+f"(d[0]), "+f"(d[1]), "+f"(d[2]), "+f"(d[3])
        : "r"(a[0]), "r"(a[1]), "r"(a[2]), "r"(a[3]), "r"(b[0]), "r"(b[1]));
}

// ---------------------------------------------------------------------------
// K1 "prep": fused pool (+bf16), Wa->bf16 convert, h2a.  (round-11 version)
// ---------------------------------------------------------------------------
#define PREP_POOL  4096
#define PREP_CONV  4352
#define PREP_TOTAL 4864

__global__ __launch_bounds__(256) void prep_kernel(const float* __restrict__ att_v,
                                                   const float* __restrict__ Wa,
                                                   const float* __restrict__ h,
                                                   const float* __restrict__ Wh,
                                                   const float* __restrict__ bh,
                                                   const float* __restrict__ ba) {
    __shared__ union {
        struct { float4 raw[32 * 49]; float pooled[32][51]; } pool;
        struct { float sh[16][132];  float sw[16][132]; }    h2a;
    } u;

    int blk = blockIdx.x;
    int tid = threadIdx.x;

    if (blk < PREP_POOL) {
        int c0 = (blk & 15) * 32;
        int b  = blk >> 4;
        const float4* base = (const float4*)(att_v + ((size_t)b * Cn + c0) * HWn);
        uint32_t raw_s = smem_u32(u.pool.raw);

#pragma unroll
        for (int t = 0; t < 7; ++t) {
            int idx = tid + t * 256;
            if (t < 6 || idx < 1568)
                cp16(raw_s + idx * 16, base + idx);
        }
        asm volatile("cp.async.commit_group;" ::: "memory");
        asm volatile("cp.async.wait_group 0;" ::: "memory");
        __syncthreads();

        int cl = tid >> 3;
        int ii = tid & 7;
        if (ii < 7) {
            const float4* p = &u.pool.raw[cl * 49 + ii * 7];
            float4 v0 = p[0], v1 = p[1], v2 = p[2], v3 = p[3],
                   v4 = p[4], v5 = p[5], v6 = p[6];
            float r0 = (v0.x + v0.y + v3.z + v3.w) * 0.25f;
            float r1 = (v0.z + v0.w + v4.x + v4.y) * 0.25f;
            float r2 = (v1.x + v1.y + v4.z + v4.w) * 0.25f;
            float r3 = (v1.z + v1.w + v5.x + v5.y) * 0.25f;
            float r4 = (v2.x + v2.y + v5.z + v5.w) * 0.25f;
            float r5 = (v2.z + v2.w + v6.x + v6.y) * 0.25f;
            float r6 = (v3.x + v3.y + v6.z + v6.w) * 0.25f;
            float* row = &u.pool.pooled[cl][ii * 7];
            row[0] = r0; row[1] = r1; row[2] = r2; row[3] = r3;
            row[4] = r4; row[5] = r5; row[6] = r6;
        }
        __syncthreads();
        for (int idx = tid; idx < Nn * 8; idx += 256) {
            int n = idx >> 3, c4 = idx & 7;
            float4 v;
            v.x = u.pool.pooled[c4 * 4 + 0][n];
            v.y = u.pool.pooled[c4 * 4 + 1][n];
            v.z = u.pool.pooled[c4 * 4 + 2][n];
            v.w = u.pool.pooled[c4 * 4 + 3][n];
            size_t o = (size_t)(b * Nn + n) * Cn + c0 + c4 * 4;
            *(float4*)(g_a + o) = v;
            __nv_bfloat162 lo(__float2bfloat16_rn(v.x), __float2bfloat16_rn(v.y));
            __nv_bfloat162 hi(__float2bfloat16_rn(v.z), __float2bfloat16_rn(v.w));
            uint2 pk;
            pk.x = *(uint32_t*)&lo;
            pk.y = *(uint32_t*)&hi;
            *(uint2*)(g_ab + o) = pk;
        }
    } else if (blk < PREP_CONV) {
        int i = (blk - PREP_POOL) * 1024 + tid * 4;
        float4 v = *(const float4*)(Wa + i);
        __nv_bfloat162 lo(__float2bfloat16_rn(v.x), __float2bfloat16_rn(v.y));
        __nv_bfloat162 hi(__float2bfloat16_rn(v.z), __float2bfloat16_rn(v.w));
        uint2 pk;
        pk.x = *(uint32_t*)&lo;
        pk.y = *(uint32_t*)&hi;
        *(uint2*)(g_wb + i) = pk;
    } else {
        int blk2 = blk - PREP_CONV;
        int d0 = (blk2 >> 4) * 16, b0 = (blk2 & 15) * 16;
        int tx = tid & 15, ty = tid >> 4;
        float acc = 0.f;

        for (int c0 = 0; c0 < Cn; c0 += 128) {
#pragma unroll
            for (int p = 0; p < 2; ++p) {
                int i = tid + p * 256;
                int r = i >> 5;
                int cc = (i & 31) * 4;
                *(float4*)&u.h2a.sh[r][cc] = *(const float4*)&h [(size_t)(b0 + r) * Cn + c0 + cc];
                *(float4*)&u.h2a.sw[r][cc] = *(const float4*)&Wh[(size_t)(d0 + r) * Cn + c0 + cc];
            }
            __syncthreads();
#pragma unroll
            for (int c = 0; c < 128; ++c) acc += u.h2a.sh[ty][c] * u.h2a.sw[tx][c];
            __syncthreads();
        }
        int d = d0 + tx, b = b0 + ty;
        g_ah[(size_t)b * Cn + d] = acc + bh[d] + ba[d];
    }
}

// ---------------------------------------------------------------------------
// K3: bf16 mma.sync GEMM + tanh + dot(Wd). BM=128, BN=64, BK=64.
// 512 threads = 16 warps as 4(M) x 4(C: 16 cols each) -> 32 warps/SM at 2 CTAs.
// 3-stage cp.async ring, XOR-swizzled 128B-pitch smem, 1 barrier/stage.
// grid (8, 98).
// ---------------------------------------------------------------------------
#define STG_A    16384       // 128 rows * 128B
#define STG_B    8192        // 64 rows * 128B
#define STG_BOTH 24576
#define OFF_AH   73728       // 3 stages * 24576
#define OFF_WD   74752       // + 4*64*4
#define SMEM_SZ  75264

__global__ __launch_bounds__(512, 2) void gemm_score_kernel(const float* __restrict__ Wd) {
    extern __shared__ __align__(16) char smem[];
    uint32_t sb = smem_u32(smem);
    float* sAh = (float*)(smem + OFF_AH);
    float* sWd = (float*)(smem + OFF_WD);

    int tid  = threadIdx.x;
    int lane = tid & 31;
    int warp = tid >> 5;           // 0..15
    int warpM = warp & 3;          // 0..3 (32 rows each)
    int warpC = warp >> 2;         // 0..3 (16 cols each)
    int rowBase = blockIdx.y * 128;
    int colBase = blockIdx.x * 64;
    int b0 = rowBase / Nn;

    if (tid < 4 * 64) {
        int bb = tid >> 6, c = tid & 63;
        int b = b0 + bb;
        sAh[tid] = (b < Bn) ? g_ah[(size_t)b * Cn + colBase + c] : 0.f;
    }
    if (tid < 64) sWd[tid] = Wd[colBase + tid];

    const __nv_bfloat16* gA = g_ab + (size_t)rowBase * Cn;
    const __nv_bfloat16* gB = g_wb + (size_t)colBase * Cn;

    // cp.async: 1536 16B chunks per stage (1024 A + 512 B), 3 per thread
    auto load_stage = [&](int s, int buf) {
        uint32_t base = sb + buf * STG_BOTH;
#pragma unroll
        for (int t = 0; t < 2; ++t) {
            int c2 = tid + t * 512;                 // 0..1023 (A)
            int r  = c2 >> 3;
            int cc = c2 & 7;
            uint32_t dsw = (uint32_t)(r * 128 + ((cc ^ (r & 7)) << 4));
            cp16(base + dsw, gA + (size_t)r * Cn + s * 64 + cc * 8);
        }
        {
            int c2 = tid;                            // 0..511 (B)
            int r  = c2 >> 3;
            int cc = c2 & 7;
            uint32_t dsw = (uint32_t)(r * 128 + ((cc ^ (r & 7)) << 4));
            cp16(base + STG_A + dsw, gB + (size_t)r * Cn + s * 64 + cc * 8);
        }
        asm volatile("cp.async.commit_group;" ::: "memory");
    };

    float acc[2][2][4];
#pragma unroll
    for (int mi = 0; mi < 2; ++mi)
#pragma unroll
        for (int ni = 0; ni < 2; ++ni)
#pragma unroll
            for (int q = 0; q < 4; ++q) acc[mi][ni][q] = 0.f;

    uint32_t s7 = lane & 7;
    uint32_t rowA = (uint32_t)(warpM * 32 + (lane & 15)) * 128;
    uint32_t rowB = STG_A +
                    (uint32_t)(warpC * 16 + ((lane >> 4) << 3) + (lane & 7)) * 128;
    uint32_t chA = lane >> 4;
    uint32_t chB = (lane >> 3) & 1;

    load_stage(0, 0);
    load_stage(1, 1);

#pragma unroll 1
    for (int s = 0; s < 8; ++s) {
        int buf = s - (s >= 3 ? 3 : 0) - (s >= 6 ? 3 : 0);   // s % 3
        if (s < 7) asm volatile("cp.async.wait_group 1;" ::: "memory");
        else       asm volatile("cp.async.wait_group 0;" ::: "memory");
        __syncthreads();

        uint32_t stage = sb + (uint32_t)buf * STG_BOTH;
#pragma unroll
        for (int kk = 0; kk < 4; ++kk) {       // four k16 slices of BK=64
            uint32_t cA = (((2 * kk + chA) ^ s7) << 4);
            uint32_t cB = (((2 * kk + chB) ^ s7) << 4);
            uint32_t af[2][4], bf[2][2];
#pragma unroll
            for (int mi = 0; mi < 2; ++mi)
                ldsm4(af[mi][0], af[mi][1], af[mi][2], af[mi][3],
                      stage + rowA + mi * (16 * 128) + cA);
            ldsm4(bf[0][0], bf[0][1], bf[1][0], bf[1][1], stage + rowB + cB);
#pragma unroll
            for (int mi = 0; mi < 2; ++mi)
#pragma unroll
                for (int ni = 0; ni < 2; ++ni)
                    mma_bf16(acc[mi][ni], af[mi], bf[ni]);
        }
        if (s + 2 < 8) {
            int nbuf = buf + 2; if (nbuf >= 3) nbuf -= 3;
            load_stage(s + 2, nbuf);
        }
    }

    // Epilogue: tanh(av + ah) . Wd -> per-row partial over this warp's 16 cols
    int gid = lane >> 2;
    int kq0 = (lane & 3) * 2;
    int slice = blockIdx.x * 4 + warpC;      // 0..31
#pragma unroll
    for (int mi = 0; mi < 2; ++mi) {
#pragma unroll
        for (int hh = 0; hh < 2; ++hh) {
            int rloc = warpM * 32 + mi * 16 + hh * 8 + gid;
            int grow = rowBase + rloc;
            int bb = grow / Nn - b0;
            float s = 0.f;
#pragma unroll
            for (int ni = 0; ni < 2; ++ni) {
                int cl = warpC * 16 + ni * 8 + kq0;
                s += fast_tanh(acc[mi][ni][hh * 2 + 0] + sAh[bb * 64 + cl])     * sWd[cl];
                s += fast_tanh(acc[mi][ni][hh * 2 + 1] + sAh[bb * 64 + cl + 1]) * sWd[cl + 1];
            }
            s += __shfl_xor_sync(0xffffffffu, s, 1);
            s += __shfl_xor_sync(0xffffffffu, s, 2);
            if ((lane & 3) == 0)
                g_spart[(size_t)slice * Mrows + grow] = s;
        }
    }
}

// ---------------------------------------------------------------------------
// K4: scores = sum(32 partials) + bd; warp softmax; float4 einsum
// ---------------------------------------------------------------------------
__global__ __launch_bounds__(128) void softmax_out_kernel(const float* __restrict__ bd,
                                                          float* __restrict__ out) {
    int b   = blockIdx.x;
    int tid = threadIdx.x;
    __shared__ float w[Nn];
    __shared__ float sinv_s;

    if (tid < Nn) {
        float s = bd[0];
#pragma unroll
        for (int i = 0; i < 32; ++i) s += g_spart[(size_t)i * Mrows + b * Nn + tid];
        w[tid] = s;
    }
    __syncthreads();
    if (tid < 32) {
        float x = w[tid];
        float y = (tid + 32 < Nn) ? w[tid + 32] : -1e30f;
        float m = fmaxf(x, y);
#pragma unroll
        for (int off = 16; off > 0; off >>= 1)
            m = fmaxf(m, __shfl_xor_sync(0xffffffffu, m, off));
        float e0 = __expf(x - m);
        float e1 = __expf(y - m);
        float s = e0 + e1;
#pragma unroll
        for (int off = 16; off > 0; off >>= 1)
            s += __shfl_xor_sync(0xffffffffu, s, off);
        w[tid] = e0;
        if (tid + 32 < Nn) w[tid + 32] = e1;
        if (tid == 0) sinv_s = 1.0f / s;
    }
    __syncthreads();
    float inv = sinv_s;

    int c = tid * 4;
    const float* ab = g_a + (size_t)b * Nn * Cn + c;
    float4 o = make_float4(0.f, 0.f, 0.f, 0.f);
#pragma unroll 7
    for (int n = 0; n < Nn; ++n) {
        float4 v = *(const float4*)(ab + (size_t)n * Cn);
        float wn = w[n];
        o.x += v.x * wn; o.y += v.y * wn; o.z += v.z * wn; o.w += v.w * wn;
    }
    o.x *= inv; o.y *= inv; o.z *= inv; o.w *= inv;
    *(float4*)(out + (size_t)b * Cn + c) = o;
}

// ---------------------------------------------------------------------------
extern "C" void kernel_launch(void* const* d_in, const int* in_sizes, int n_in,
                              void* d_out, int out_size) {
    const float* att_v = (const float*)d_in[0];
    const float* h     = (const float*)d_in[1];
    const float* Wa    = (const float*)d_in[2];
    const float* ba    = (const float*)d_in[3];
    const float* Wh    = (const float*)d_in[4];
    const float* bh    = (const float*)d_in[5];
    const float* Wd    = (const float*)d_in[6];
    const float* bd    = (const float*)d_in[7];
    float* out = (float*)d_out;

    cudaFuncSetAttribute(gemm_score_kernel,
                         cudaFuncAttributeMaxDynamicSharedMemorySize, SMEM_SZ);

    prep_kernel       <<<PREP_TOTAL, 256>>>(att_v, Wa, h, Wh, bh, ba);
    gemm_score_kernel <<<dim3(8, 98), 512, SMEM_SZ>>>(Wd);
    softmax_out_kernel<<<256, 128>>>(bd, out);
}

// round 16
// speedup vs baseline: 1.2021x; 1.1733x over previous
#include <cuda_runtime.h>
#include <cuda_bf16.h>
#include <cstdint>

// Problem constants
#define Bn   256
#define Cn   512
#define Nn   49          // 7x7 attention positions
#define HWn  196         // 14*14
#define Mrows (Bn*Nn)    // 12544

// Scratch (no allocation allowed)
__device__ float          g_a [Mrows * Cn];    // pooled fp32 (final einsum)
__device__ __nv_bfloat16  g_ab[Mrows * Cn];    // pooled bf16 (GEMM A)
__device__ __nv_bfloat16  g_wb[Cn * Cn];       // Wa bf16 (GEMM B)
__device__ float          g_ah[Bn * Cn];       // h@Wh^T + bh + ba
__device__ float          g_spart[16 * Mrows]; // per (col-tile, col-half) partials

__device__ __forceinline__ float fast_tanh(float x) {
    float y; asm("tanh.approx.f32 %0, %1;" : "=f"(y) : "f"(x)); return y;
}
__device__ __forceinline__ uint32_t smem_u32(const void* p) {
    uint32_t a;
    asm("{ .reg .u64 t; cvta.to.shared.u64 t, %1; cvt.u32.u64 %0, t; }" : "=r"(a) : "l"(p));
    return a;
}
__device__ __forceinline__ void cp16(uint32_t dst, const void* src) {
    asm volatile("cp.async.cg.shared.global [%0], [%1], 16;" :: "r"(dst), "l"(src));
}
__device__ __forceinline__ void ldsm4(uint32_t& r0, uint32_t& r1, uint32_t& r2,
                                      uint32_t& r3, uint32_t addr) {
    asm volatile("ldmatrix.sync.aligned.m8n8.x4.shared.b16 {%0,%1,%2,%3}, [%4];"
                 : "=r"(r0), "=r"(r1), "=r"(r2), "=r"(r3) : "r"(addr));
}
__device__ __forceinline__ void mma_bf16(float* d, const uint32_t* a, const uint32_t* b) {
    asm volatile(
        "mma.sync.aligned.m16n8k16.row.col.f32.bf16.bf16.f32 "
        "{%0,%1,%2,%3}, {%4,%5,%6,%7}, {%8,%9}, {%0,%1,%2,%3};"
        : "+f"(d[0]), "+f"(d[1]), "+f"(d[2]), "+f"(d[3])
        : "r"(a[0]), "r"(a[1]), "r"(a[2]), "r"(a[3]), "r"(b[0]), "r"(b[1]));
}

// ---------------------------------------------------------------------------
// K1 "prep": pool with intra-block 2-deep cp.async ring (4 c-tile stages per
// block), Wa->bf16 convert, h2a.  Flat 1D grid, dynamic smem.
//   blk [0, 1024):      pool  (b = blk>>2, quarter = blk&3 -> c-tiles 4q..4q+3)
//   blk [1024, 1280):   Wa convert chunk
//   blk [1280, 1792):   h2a block
// ---------------------------------------------------------------------------
#define PREP_POOL  1024
#define PREP_CONV  1280
#define PREP_TOTAL 1792
#define POOL_STG_B 25088     // 1568 float4 per stage
#define POOL_POOLED_OFF 50176
#define PREP_SMEM  56832     // 2*25088 + 32*51*4 (h2a needs only 16.9KB)

__global__ __launch_bounds__(256) void prep_kernel(const float* __restrict__ att_v,
                                                   const float* __restrict__ Wa,
                                                   const float* __restrict__ h,
                                                   const float* __restrict__ Wh,
                                                   const float* __restrict__ bh,
                                                   const float* __restrict__ ba) {
    extern __shared__ __align__(16) char psm[];
    int blk = blockIdx.x;
    int tid = threadIdx.x;

    if (blk < PREP_POOL) {
        float4* raw = (float4*)psm;                              // [2][1568]
        float (*pooled)[51] = (float(*)[51])(psm + POOL_POOLED_OFF);
        int b       = blk >> 2;
        int quarter = blk & 3;
        const float* avbase = att_v + (size_t)b * Cn * HWn;
        uint32_t raw_s = smem_u32(psm);

        auto load_stage = [&](int s) {
            const float4* base =
                (const float4*)(avbase + (size_t)(quarter * 4 + s) * 32 * HWn);
            uint32_t dst = raw_s + (uint32_t)(s & 1) * POOL_STG_B;
#pragma unroll
            for (int t = 0; t < 7; ++t) {
                int idx = tid + t * 256;
                if (t < 6 || idx < 1568)
                    cp16(dst + idx * 16, base + idx);
            }
            asm volatile("cp.async.commit_group;" ::: "memory");
        };

        load_stage(0);
#pragma unroll 1
        for (int s = 0; s < 4; ++s) {
            if (s < 3) {
                load_stage(s + 1);
                asm volatile("cp.async.wait_group 1;" ::: "memory");
            } else {
                asm volatile("cp.async.wait_group 0;" ::: "memory");
            }
            __syncthreads();                        // stage s data visible

            const float4* rb = raw + (s & 1) * 1568;
            int cl = tid >> 3;
            int ii = tid & 7;
            if (ii < 7) {
                const float4* p = rb + cl * 49 + ii * 7;
                float4 v0 = p[0], v1 = p[1], v2 = p[2], v3 = p[3],
                       v4 = p[4], v5 = p[5], v6 = p[6];
                float r0 = (v0.x + v0.y + v3.z + v3.w) * 0.25f;
                float r1 = (v0.z + v0.w + v4.x + v4.y) * 0.25f;
                float r2 = (v1.x + v1.y + v4.z + v4.w) * 0.25f;
                float r3 = (v1.z + v1.w + v5.x + v5.y) * 0.25f;
                float r4 = (v2.x + v2.y + v5.z + v5.w) * 0.25f;
                float r5 = (v2.z + v2.w + v6.x + v6.y) * 0.25f;
                float r6 = (v3.x + v3.y + v6.z + v6.w) * 0.25f;
                float* row = &pooled[cl][ii * 7];
                row[0] = r0; row[1] = r1; row[2] = r2; row[3] = r3;
                row[4] = r4; row[5] = r5; row[6] = r6;
            }
            __syncthreads();                        // pooled complete

            int c0 = (quarter * 4 + s) * 32;
            for (int idx = tid; idx < Nn * 8; idx += 256) {
                int n = idx >> 3, c4 = idx & 7;
                float4 v;
                v.x = pooled[c4 * 4 + 0][n];
                v.y = pooled[c4 * 4 + 1][n];
                v.z = pooled[c4 * 4 + 2][n];
                v.w = pooled[c4 * 4 + 3][n];
                size_t o = (size_t)(b * Nn + n) * Cn + c0 + c4 * 4;
                *(float4*)(g_a + o) = v;
                __nv_bfloat162 lo(__float2bfloat16_rn(v.x), __float2bfloat16_rn(v.y));
                __nv_bfloat162 hi(__float2bfloat16_rn(v.z), __float2bfloat16_rn(v.w));
                uint2 pk;
                pk.x = *(uint32_t*)&lo;
                pk.y = *(uint32_t*)&hi;
                *(uint2*)(g_ab + o) = pk;
            }
            __syncthreads();                        // pooled consumed
        }
    } else if (blk < PREP_CONV) {
        // ---- Wa fp32 -> bf16, 1024 floats per block ----
        int i = (blk - PREP_POOL) * 1024 + tid * 4;
        float4 v = *(const float4*)(Wa + i);
        __nv_bfloat162 lo(__float2bfloat16_rn(v.x), __float2bfloat16_rn(v.y));
        __nv_bfloat162 hi(__float2bfloat16_rn(v.z), __float2bfloat16_rn(v.w));
        uint2 pk;
        pk.x = *(uint32_t*)&lo;
        pk.y = *(uint32_t*)&hi;
        *(uint2*)(g_wb + i) = pk;
    } else {
        // ---- h2a: g_ah[b,d] = h@Wh^T + bh + ba ----
        float (*sh)[132] = (float(*)[132])psm;
        float (*sw)[132] = (float(*)[132])(psm + 16 * 132 * 4);
        int blk2 = blk - PREP_CONV;                 // 0..511
        int d0 = (blk2 >> 4) * 16, b0 = (blk2 & 15) * 16;
        int tx = tid & 15, ty = tid >> 4;
        float acc = 0.f;

        for (int c0 = 0; c0 < Cn; c0 += 128) {
#pragma unroll
            for (int p = 0; p < 2; ++p) {
                int i = tid + p * 256;
                int r = i >> 5;
                int cc = (i & 31) * 4;
                *(float4*)&sh[r][cc] = *(const float4*)&h [(size_t)(b0 + r) * Cn + c0 + cc];
                *(float4*)&sw[r][cc] = *(const float4*)&Wh[(size_t)(d0 + r) * Cn + c0 + cc];
            }
            __syncthreads();
#pragma unroll
            for (int c = 0; c < 128; ++c) acc += sh[ty][c] * sw[tx][c];
            __syncthreads();
        }
        int d = d0 + tx, b = b0 + ty;
        g_ah[(size_t)b * Cn + d] = acc + bh[d] + ba[d];
    }
}

// ---------------------------------------------------------------------------
// K3: bf16 mma.sync GEMM + tanh + dot(Wd). BM=128, BN=64, BK=64. (round-11)
// 3-stage cp.async ring, XOR-swizzled 128B-pitch smem, 1 barrier/stage.
// 8 warps = 4(M) x 2(N:32 each). grid (8, 98), 256 threads.
// ---------------------------------------------------------------------------
#define STG_A    16384       // 128 rows * 128B
#define STG_B    8192        // 64 rows * 128B
#define STG_BOTH 24576
#define OFF_AH   73728       // 3 stages * 24576
#define OFF_WD   74752       // + 4*64*4
#define SMEM_SZ  75264

__global__ __launch_bounds__(256, 2) void gemm_score_kernel(const float* __restrict__ Wd) {
    extern __shared__ __align__(16) char smem[];
    uint32_t sb = smem_u32(smem);
    float* sAh = (float*)(smem + OFF_AH);
    float* sWd = (float*)(smem + OFF_WD);

    int tid  = threadIdx.x;
    int lane = tid & 31;
    int warp = tid >> 5;
    int warpM = warp & 3;
    int warpC = warp >> 2;
    int rowBase = blockIdx.y * 128;
    int colBase = blockIdx.x * 64;
    int b0 = rowBase / Nn;

    for (int i = tid; i < 4 * 64; i += 256) {
        int bb = i >> 6, c = i & 63;
        int b = b0 + bb;
        sAh[i] = (b < Bn) ? g_ah[(size_t)b * Cn + colBase + c] : 0.f;
    }
    if (tid < 64) sWd[tid] = Wd[colBase + tid];

    const __nv_bfloat16* gA = g_ab + (size_t)rowBase * Cn;
    const __nv_bfloat16* gB = g_wb + (size_t)colBase * Cn;

    auto load_stage = [&](int s, int buf) {
        uint32_t base = sb + buf * STG_BOTH;
#pragma unroll
        for (int t = 0; t < 4; ++t) {
            int c2 = tid + t * 256;                 // 0..1023 (A)
            int r  = c2 >> 3;
            int cc = c2 & 7;
            uint32_t dsw = (uint32_t)(r * 128 + ((cc ^ (r & 7)) << 4));
            cp16(base + dsw, gA + (size_t)r * Cn + s * 64 + cc * 8);
        }
#pragma unroll
        for (int t = 0; t < 2; ++t) {
            int c2 = tid + t * 256;                 // 0..511 (B)
            int r  = c2 >> 3;
            int cc = c2 & 7;
            uint32_t dsw = (uint32_t)(r * 128 + ((cc ^ (r & 7)) << 4));
            cp16(base + STG_A + dsw, gB + (size_t)r * Cn + s * 64 + cc * 8);
        }
        asm volatile("cp.async.commit_group;" ::: "memory");
    };

    float acc[2][4][4];
#pragma unroll
    for (int mi = 0; mi < 2; ++mi)
#pragma unroll
        for (int ni = 0; ni < 4; ++ni)
#pragma unroll
            for (int q = 0; q < 4; ++q) acc[mi][ni][q] = 0.f;

    uint32_t s7 = lane & 7;
    uint32_t rowA = (uint32_t)(warpM * 32 + (lane & 15)) * 128;
    uint32_t rowB = STG_A +
                    (uint32_t)(warpC * 32 + ((lane >> 4) << 3) + (lane & 7)) * 128;
    uint32_t chA = lane >> 4;
    uint32_t chB = (lane >> 3) & 1;

    load_stage(0, 0);
    load_stage(1, 1);

#pragma unroll 1
    for (int s = 0; s < 8; ++s) {
        int buf = s - (s >= 3 ? 3 : 0) - (s >= 6 ? 3 : 0);   // s % 3
        if (s < 7) asm volatile("cp.async.wait_group 1;" ::: "memory");
        else       asm volatile("cp.async.wait_group 0;" ::: "memory");
        __syncthreads();

        uint32_t stage = sb + (uint32_t)buf * STG_BOTH;
#pragma unroll
        for (int kk = 0; kk < 4; ++kk) {
            uint32_t cA = (((2 * kk + chA) ^ s7) << 4);
            uint32_t cB = (((2 * kk + chB) ^ s7) << 4);
            uint32_t af[2][4], bf[4][2];
#pragma unroll
            for (int mi = 0; mi < 2; ++mi)
                ldsm4(af[mi][0], af[mi][1], af[mi][2], af[mi][3],
                      stage + rowA + mi * (16 * 128) + cA);
#pragma unroll
            for (int np = 0; np < 2; ++np)
                ldsm4(bf[2 * np][0], bf[2 * np][1], bf[2 * np + 1][0], bf[2 * np + 1][1],
                      stage + rowB + np * (16 * 128) + cB);
#pragma unroll
            for (int mi = 0; mi < 2; ++mi)
#pragma unroll
                for (int ni = 0; ni < 4; ++ni)
                    mma_bf16(acc[mi][ni], af[mi], bf[ni]);
        }
        if (s + 2 < 8) {
            int nbuf = buf + 2; if (nbuf >= 3) nbuf -= 3;
            load_stage(s + 2, nbuf);
        }
    }

    // Epilogue
    int gid = lane >> 2;
    int kq0 = (lane & 3) * 2;
    int slice = blockIdx.x * 2 + warpC;      // 0..15
#pragma unroll
    for (int mi = 0; mi < 2; ++mi) {
#pragma unroll
        for (int hh = 0; hh < 2; ++hh) {
            int rloc = warpM * 32 + mi * 16 + hh * 8 + gid;
            int grow = rowBase + rloc;
            int bb = grow / Nn - b0;
            float s = 0.f;
#pragma unroll
            for (int ni = 0; ni < 4; ++ni) {
                int cl = warpC * 32 + ni * 8 + kq0;
                s += fast_tanh(acc[mi][ni][hh * 2 + 0] + sAh[bb * 64 + cl])     * sWd[cl];
                s += fast_tanh(acc[mi][ni][hh * 2 + 1] + sAh[bb * 64 + cl + 1]) * sWd[cl + 1];
            }
            s += __shfl_xor_sync(0xffffffffu, s, 1);
            s += __shfl_xor_sync(0xffffffffu, s, 2);
            if ((lane & 3) == 0)
                g_spart[(size_t)slice * Mrows + grow] = s;
        }
    }
}

// ---------------------------------------------------------------------------
// K4: scores = sum(16 partials) + bd; warp softmax; float4 einsum (round-11)
// ---------------------------------------------------------------------------
__global__ __launch_bounds__(128) void softmax_out_kernel(const float* __restrict__ bd,
                                                          float* __restrict__ out) {
    int b   = blockIdx.x;
    int tid = threadIdx.x;
    __shared__ float w[Nn];
    __shared__ float sinv_s;

    if (tid < Nn) {
        float s = bd[0];
#pragma unroll
        for (int i = 0; i < 16; ++i) s += g_spart[(size_t)i * Mrows + b * Nn + tid];
        w[tid] = s;
    }
    __syncthreads();
    if (tid < 32) {
        float x = w[tid];
        float y = (tid + 32 < Nn) ? w[tid + 32] : -1e30f;
        float m = fmaxf(x, y);
#pragma unroll
        for (int off = 16; off > 0; off >>= 1)
            m = fmaxf(m, __shfl_xor_sync(0xffffffffu, m, off));
        float e0 = __expf(x - m);
        float e1 = __expf(y - m);
        float s = e0 + e1;
#pragma unroll
        for (int off = 16; off > 0; off >>= 1)
            s += __shfl_xor_sync(0xffffffffu, s, off);
        w[tid] = e0;
        if (tid + 32 < Nn) w[tid + 32] = e1;
        if (tid == 0) sinv_s = 1.0f / s;
    }
    __syncthreads();
    float inv = sinv_s;

    int c = tid * 4;
    const float* ab = g_a + (size_t)b * Nn * Cn + c;
    float4 o = make_float4(0.f, 0.f, 0.f, 0.f);
#pragma unroll 7
    for (int n = 0; n < Nn; ++n) {
        float4 v = *(const float4*)(ab + (size_t)n * Cn);
        float wn = w[n];
        o.x += v.x * wn; o.y += v.y * wn; o.z += v.z * wn; o.w += v.w * wn;
    }
    o.x *= inv; o.y *= inv; o.z *= inv; o.w *= inv;
    *(float4*)(out + (size_t)b * Cn + c) = o;
}

// ---------------------------------------------------------------------------
extern "C" void kernel_launch(void* const* d_in, const int* in_sizes, int n_in,
                              void* d_out, int out_size) {
    const float* att_v = (const float*)d_in[0];
    const float* h     = (const float*)d_in[1];
    const float* Wa    = (const float*)d_in[2];
    const float* ba    = (const float*)d_in[3];
    const float* Wh    = (const float*)d_in[4];
    const float* bh    = (const float*)d_in[5];
    const float* Wd    = (const float*)d_in[6];
    const float* bd    = (const float*)d_in[7];
    float* out = (float*)d_out;

    cudaFuncSetAttribute(prep_kernel,
                         cudaFuncAttributeMaxDynamicSharedMemorySize, PREP_SMEM);
    cudaFuncSetAttribute(gemm_score_kernel,
                         cudaFuncAttributeMaxDynamicSharedMemorySize, SMEM_SZ);

    prep_kernel       <<<PREP_TOTAL, 256, PREP_SMEM>>>(att_v, Wa, h, Wh, bh, ba);
    gemm_score_kernel <<<dim3(8, 98), 256, SMEM_SZ>>>(Wd);
    softmax_out_kernel<<<256, 128>>>(bd, out);
}

// round 17
// speedup vs baseline: 1.2333x; 1.0259x over previous
#include <cuda_runtime.h>
#include <cuda_bf16.h>
#include <cstdint>

// Problem constants
#define Bn   256
#define Cn   512
#define Nn   49          // 7x7 attention positions
#define HWn  196         // 14*14
#define Mrows (Bn*Nn)    // 12544

// Scratch (no allocation allowed)
__device__ float          g_a [Mrows * Cn];    // pooled fp32 (final einsum)
__device__ __nv_bfloat16  g_ab[Mrows * Cn];    // pooled bf16 (GEMM A)
__device__ __nv_bfloat16  g_wb[Cn * Cn];       // Wa bf16 (GEMM B)
__device__ float          g_ah[Bn * Cn];       // h@Wh^T + bh + ba
__device__ float          g_spart[16 * Mrows]; // per (col-tile, col-half) partials

__device__ __forceinline__ float fast_tanh(float x) {
    float y; asm("tanh.approx.f32 %0, %1;" : "=f"(y) : "f"(x)); return y;
}
__device__ __forceinline__ uint32_t smem_u32(const void* p) {
    uint32_t a;
    asm("{ .reg .u64 t; cvta.to.shared.u64 t, %1; cvt.u32.u64 %0, t; }" : "=r"(a) : "l"(p));
    return a;
}
__device__ __forceinline__ void cp16(uint32_t dst, const void* src) {
    asm volatile("cp.async.cg.shared.global [%0], [%1], 16;" :: "r"(dst), "l"(src));
}
__device__ __forceinline__ void ldsm4(uint32_t& r0, uint32_t& r1, uint32_t& r2,
                                      uint32_t& r3, uint32_t addr) {
    asm volatile("ldmatrix.sync.aligned.m8n8.x4.shared.b16 {%0,%1,%2,%3}, [%4];"
                 : "=r"(r0), "=r"(r1), "=r"(r2), "=r"(r3) : "r"(addr));
}
__device__ __forceinline__ void mma_bf16(float* d, const uint32_t* a, const uint32_t* b) {
    asm volatile(
        "mma.sync.aligned.m16n8k16.row.col.f32.bf16.bf16.f32 "
        "{%0,%1,%2,%3}, {%4,%5,%6,%7}, {%8,%9}, {%0,%1,%2,%3};"
        : "+f"(d[0]), "+f"(d[1]), "+f"(d[2]), "+f"(d[3])
        : "r"(a[0]), "r"(a[1]), "r"(a[2]), "r"(a[3]), "r"(b[0]), "r"(b[1]));
}

// ---------------------------------------------------------------------------
// K1 "prep": pool with intra-block 2-deep cp.async ring (4 c-tile stages per
// block), Wa->bf16 convert, h2a.  Flat 1D grid, dynamic smem. (round-16)
// ---------------------------------------------------------------------------
#define PREP_POOL  1024
#define PREP_CONV  1280
#define PREP_TOTAL 1792
#define POOL_STG_B 25088     // 1568 float4 per stage
#define POOL_POOLED_OFF 50176
#define PREP_SMEM  56832

__global__ __launch_bounds__(256) void prep_kernel(const float* __restrict__ att_v,
                                                   const float* __restrict__ Wa,
                                                   const float* __restrict__ h,
                                                   const float* __restrict__ Wh,
                                                   const float* __restrict__ bh,
                                                   const float* __restrict__ ba) {
    extern __shared__ __align__(16) char psm[];
    int blk = blockIdx.x;
    int tid = threadIdx.x;

    if (blk < PREP_POOL) {
        float4* raw = (float4*)psm;                              // [2][1568]
        float (*pooled)[51] = (float(*)[51])(psm + POOL_POOLED_OFF);
        int b       = blk >> 2;
        int quarter = blk & 3;
        const float* avbase = att_v + (size_t)b * Cn * HWn;
        uint32_t raw_s = smem_u32(psm);

        auto load_stage = [&](int s) {
            const float4* base =
                (const float4*)(avbase + (size_t)(quarter * 4 + s) * 32 * HWn);
            uint32_t dst = raw_s + (uint32_t)(s & 1) * POOL_STG_B;
#pragma unroll
            for (int t = 0; t < 7; ++t) {
                int idx = tid + t * 256;
                if (t < 6 || idx < 1568)
                    cp16(dst + idx * 16, base + idx);
            }
            asm volatile("cp.async.commit_group;" ::: "memory");
        };

        load_stage(0);
#pragma unroll 1
        for (int s = 0; s < 4; ++s) {
            if (s < 3) {
                load_stage(s + 1);
                asm volatile("cp.async.wait_group 1;" ::: "memory");
            } else {
                asm volatile("cp.async.wait_group 0;" ::: "memory");
            }
            __syncthreads();                        // stage s data visible

            const float4* rb = raw + (s & 1) * 1568;
            int cl = tid >> 3;
            int ii = tid & 7;
            if (ii < 7) {
                const float4* p = rb + cl * 49 + ii * 7;
                float4 v0 = p[0], v1 = p[1], v2 = p[2], v3 = p[3],
                       v4 = p[4], v5 = p[5], v6 = p[6];
                float r0 = (v0.x + v0.y + v3.z + v3.w) * 0.25f;
                float r1 = (v0.z + v0.w + v4.x + v4.y) * 0.25f;
                float r2 = (v1.x + v1.y + v4.z + v4.w) * 0.25f;
                float r3 = (v1.z + v1.w + v5.x + v5.y) * 0.25f;
                float r4 = (v2.x + v2.y + v5.z + v5.w) * 0.25f;
                float r5 = (v2.z + v2.w + v6.x + v6.y) * 0.25f;
                float r6 = (v3.x + v3.y + v6.z + v6.w) * 0.25f;
                float* row = &pooled[cl][ii * 7];
                row[0] = r0; row[1] = r1; row[2] = r2; row[3] = r3;
                row[4] = r4; row[5] = r5; row[6] = r6;
            }
            __syncthreads();                        // pooled complete

            int c0 = (quarter * 4 + s) * 32;
            for (int idx = tid; idx < Nn * 8; idx += 256) {
                int n = idx >> 3, c4 = idx & 7;
                float4 v;
                v.x = pooled[c4 * 4 + 0][n];
                v.y = pooled[c4 * 4 + 1][n];
                v.z = pooled[c4 * 4 + 2][n];
                v.w = pooled[c4 * 4 + 3][n];
                size_t o = (size_t)(b * Nn + n) * Cn + c0 + c4 * 4;
                *(float4*)(g_a + o) = v;
                __nv_bfloat162 lo(__float2bfloat16_rn(v.x), __float2bfloat16_rn(v.y));
                __nv_bfloat162 hi(__float2bfloat16_rn(v.z), __float2bfloat16_rn(v.w));
                uint2 pk;
                pk.x = *(uint32_t*)&lo;
                pk.y = *(uint32_t*)&hi;
                *(uint2*)(g_ab + o) = pk;
            }
            __syncthreads();                        // pooled consumed
        }
    } else if (blk < PREP_CONV) {
        // ---- Wa fp32 -> bf16, 1024 floats per block ----
        int i = (blk - PREP_POOL) * 1024 + tid * 4;
        float4 v = *(const float4*)(Wa + i);
        __nv_bfloat162 lo(__float2bfloat16_rn(v.x), __float2bfloat16_rn(v.y));
        __nv_bfloat162 hi(__float2bfloat16_rn(v.z), __float2bfloat16_rn(v.w));
        uint2 pk;
        pk.x = *(uint32_t*)&lo;
        pk.y = *(uint32_t*)&hi;
        *(uint2*)(g_wb + i) = pk;
    } else {
        // ---- h2a: g_ah[b,d] = h@Wh^T + bh + ba ----
        float (*sh)[132] = (float(*)[132])psm;
        float (*sw)[132] = (float(*)[132])(psm + 16 * 132 * 4);
        int blk2 = blk - PREP_CONV;                 // 0..511
        int d0 = (blk2 >> 4) * 16, b0 = (blk2 & 15) * 16;
        int tx = tid & 15, ty = tid >> 4;
        float acc = 0.f;

        for (int c0 = 0; c0 < Cn; c0 += 128) {
#pragma unroll
            for (int p = 0; p < 2; ++p) {
                int i = tid + p * 256;
                int r = i >> 5;
                int cc = (i & 31) * 4;
                *(float4*)&sh[r][cc] = *(const float4*)&h [(size_t)(b0 + r) * Cn + c0 + cc];
                *(float4*)&sw[r][cc] = *(const float4*)&Wh[(size_t)(d0 + r) * Cn + c0 + cc];
            }
            __syncthreads();
#pragma unroll
            for (int c = 0; c < 128; ++c) acc += sh[ty][c] * sw[tx][c];
            __syncthreads();
        }
        int d = d0 + tx, b = b0 + ty;
        g_ah[(size_t)b * Cn + d] = acc + bh[d] + ba[d];
    }
}

// ---------------------------------------------------------------------------
// K3: bf16 mma.sync GEMM + tanh + dot(Wd). BM=128, BN=64, BK=64.
// 3-stage cp.async ring, XOR-swizzled 128B-pitch smem, 1 barrier/stage.
// 8 warps = 4(M) x 2(N:32 each). grid (8, 98), 256 threads.
// __launch_bounds__(256,3): cap regs at 85 -> 3 CTAs/SM (24 warps).
// ---------------------------------------------------------------------------
#define STG_A    16384       // 128 rows * 128B
#define STG_B    8192        // 64 rows * 128B
#define STG_BOTH 24576
#define OFF_AH   73728       // 3 stages * 24576
#define OFF_WD   74752       // + 4*64*4
#define SMEM_SZ  75264       // 3 CTAs * 75264 = 225.8KB <= 228KB/SM

__global__ __launch_bounds__(256, 3) void gemm_score_kernel(const float* __restrict__ Wd) {
    extern __shared__ __align__(16) char smem[];
    uint32_t sb = smem_u32(smem);
    float* sAh = (float*)(smem + OFF_AH);
    float* sWd = (float*)(smem + OFF_WD);

    int tid  = threadIdx.x;
    int lane = tid & 31;
    int warp = tid >> 5;
    int warpM = warp & 3;
    int warpC = warp >> 2;
    int rowBase = blockIdx.y * 128;
    int colBase = blockIdx.x * 64;
    int b0 = rowBase / Nn;

    for (int i = tid; i < 4 * 64; i += 256) {
        int bb = i >> 6, c = i & 63;
        int b = b0 + bb;
        sAh[i] = (b < Bn) ? g_ah[(size_t)b * Cn + colBase + c] : 0.f;
    }
    if (tid < 64) sWd[tid] = Wd[colBase + tid];

    const __nv_bfloat16* gA = g_ab + (size_t)rowBase * Cn;
    const __nv_bfloat16* gB = g_wb + (size_t)colBase * Cn;

    auto load_stage = [&](int s, int buf) {
        uint32_t base = sb + buf * STG_BOTH;
#pragma unroll
        for (int t = 0; t < 4; ++t) {
            int c2 = tid + t * 256;                 // 0..1023 (A)
            int r  = c2 >> 3;
            int cc = c2 & 7;
            uint32_t dsw = (uint32_t)(r * 128 + ((cc ^ (r & 7)) << 4));
            cp16(base + dsw, gA + (size_t)r * Cn + s * 64 + cc * 8);
        }
#pragma unroll
        for (int t = 0; t < 2; ++t) {
            int c2 = tid + t * 256;                 // 0..511 (B)
            int r  = c2 >> 3;
            int cc = c2 & 7;
            uint32_t dsw = (uint32_t)(r * 128 + ((cc ^ (r & 7)) << 4));
            cp16(base + STG_A + dsw, gB + (size_t)r * Cn + s * 64 + cc * 8);
        }
        asm volatile("cp.async.commit_group;" ::: "memory");
    };

    float acc[2][4][4];
#pragma unroll
    for (int mi = 0; mi < 2; ++mi)
#pragma unroll
        for (int ni = 0; ni < 4; ++ni)
#pragma unroll
            for (int q = 0; q < 4; ++q) acc[mi][ni][q] = 0.f;

    uint32_t s7 = lane & 7;
    uint32_t rowA = (uint32_t)(warpM * 32 + (lane & 15)) * 128;
    uint32_t rowB = STG_A +
                    (uint32_t)(warpC * 32 + ((lane >> 4) << 3) + (lane & 7)) * 128;
    uint32_t chA = lane >> 4;
    uint32_t chB = (lane >> 3) & 1;

    load_stage(0, 0);
    load_stage(1, 1);

#pragma unroll 1
    for (int s = 0; s < 8; ++s) {
        int buf = s - (s >= 3 ? 3 : 0) - (s >= 6 ? 3 : 0);   // s % 3
        if (s < 7) asm volatile("cp.async.wait_group 1;" ::: "memory");
        else       asm volatile("cp.async.wait_group 0;" ::: "memory");
        __syncthreads();

        uint32_t stage = sb + (uint32_t)buf * STG_BOTH;
#pragma unroll
        for (int kk = 0; kk < 4; ++kk) {
            uint32_t cA = (((2 * kk + chA) ^ s7) << 4);
            uint32_t cB = (((2 * kk + chB) ^ s7) << 4);
            uint32_t af[2][4], bf[4][2];
#pragma unroll
            for (int mi = 0; mi < 2; ++mi)
                ldsm4(af[mi][0], af[mi][1], af[mi][2], af[mi][3],
                      stage + rowA + mi * (16 * 128) + cA);
#pragma unroll
            for (int np = 0; np < 2; ++np)
                ldsm4(bf[2 * np][0], bf[2 * np][1], bf[2 * np + 1][0], bf[2 * np + 1][1],
                      stage + rowB + np * (16 * 128) + cB);
#pragma unroll
            for (int mi = 0; mi < 2; ++mi)
#pragma unroll
                for (int ni = 0; ni < 4; ++ni)
                    mma_bf16(acc[mi][ni], af[mi], bf[ni]);
        }
        if (s + 2 < 8) {
            int nbuf = buf + 2; if (nbuf >= 3) nbuf -= 3;
            load_stage(s + 2, nbuf);
        }
    }

    // Epilogue
    int gid = lane >> 2;
    int kq0 = (lane & 3) * 2;
    int slice = blockIdx.x * 2 + warpC;      // 0..15
#pragma unroll
    for (int mi = 0; mi < 2; ++mi) {
#pragma unroll
        for (int hh = 0; hh < 2; ++hh) {
            int rloc = warpM * 32 + mi * 16 + hh * 8 + gid;
            int grow = rowBase + rloc;
            int bb = grow / Nn - b0;
            float s = 0.f;
#pragma unroll
            for (int ni = 0; ni < 4; ++ni) {
                int cl = warpC * 32 + ni * 8 + kq0;
                s += fast_tanh(acc[mi][ni][hh * 2 + 0] + sAh[bb * 64 + cl])     * sWd[cl];
                s += fast_tanh(acc[mi][ni][hh * 2 + 1] + sAh[bb * 64 + cl + 1]) * sWd[cl + 1];
            }
            s += __shfl_xor_sync(0xffffffffu, s, 1);
            s += __shfl_xor_sync(0xffffffffu, s, 2);
            if ((lane & 3) == 0)
                g_spart[(size_t)slice * Mrows + grow] = s;
        }
    }
}

// ---------------------------------------------------------------------------
// K4: scores = sum(16 partials) + bd; warp softmax; float4 einsum
// ---------------------------------------------------------------------------
__global__ __launch_bounds__(128) void softmax_out_kernel(const float* __restrict__ bd,
                                                          float* __restrict__ out) {
    int b   = blockIdx.x;
    int tid = threadIdx.x;
    __shared__ float w[Nn];
    __shared__ float sinv_s;

    if (tid < Nn) {
        float s = bd[0];
#pragma unroll
        for (int i = 0; i < 16; ++i) s += g_spart[(size_t)i * Mrows + b * Nn + tid];
        w[tid] = s;
    }
    __syncthreads();
    if (tid < 32) {
        float x = w[tid];
        float y = (tid + 32 < Nn) ? w[tid + 32] : -1e30f;
        float m = fmaxf(x, y);
#pragma unroll
        for (int off = 16; off > 0; off >>= 1)
            m = fmaxf(m, __shfl_xor_sync(0xffffffffu, m, off));
        float e0 = __expf(x - m);
        float e1 = __expf(y - m);
        float s = e0 + e1;
#pragma unroll
        for (int off = 16; off > 0; off >>= 1)
            s += __shfl_xor_sync(0xffffffffu, s, off);
        w[tid] = e0;
        if (tid + 32 < Nn) w[tid + 32] = e1;
        if (tid == 0) sinv_s = 1.0f / s;
    }
    __syncthreads();
    float inv = sinv_s;

    int c = tid * 4;
    const float* ab = g_a + (size_t)b * Nn * Cn + c;
    float4 o = make_float4(0.f, 0.f, 0.f, 0.f);
#pragma unroll 7
    for (int n = 0; n < Nn; ++n) {
        float4 v = *(const float4*)(ab + (size_t)n * Cn);
        float wn = w[n];
        o.x += v.x * wn; o.y += v.y * wn; o.z += v.z * wn; o.w += v.w * wn;
    }
    o.x *= inv; o.y *= inv; o.z *= inv; o.w *= inv;
    *(float4*)(out + (size_t)b * Cn + c) = o;
}

// ---------------------------------------------------------------------------
extern "C" void kernel_launch(void* const* d_in, const int* in_sizes, int n_in,
                              void* d_out, int out_size) {
    const float* att_v = (const float*)d_in[0];
    const float* h     = (const float*)d_in[1];
    const float* Wa    = (const float*)d_in[2];
    const float* ba    = (const float*)d_in[3];
    const float* Wh    = (const float*)d_in[4];
    const float* bh    = (const float*)d_in[5];
    const float* Wd    = (const float*)d_in[6];
    const float* bd    = (const float*)d_in[7];
    float* out = (float*)d_out;

    cudaFuncSetAttribute(prep_kernel,
                         cudaFuncAttributeMaxDynamicSharedMemorySize, PREP_SMEM);
    cudaFuncSetAttribute(gemm_score_kernel,
                         cudaFuncAttributeMaxDynamicSharedMemorySize, SMEM_SZ);

    prep_kernel       <<<PREP_TOTAL, 256, PREP_SMEM>>>(att_v, Wa, h, Wh, bh, ba);
    gemm_score_kernel <<<dim3(8, 98), 256, SMEM_SZ>>>(Wd);
    softmax_out_kernel<<<256, 128>>>(bd, out);
}